// round 1
// baseline (speedup 1.0000x reference)
#include <cuda_runtime.h>
#include <cuda_bf16.h>
#include <cstdint>

#define CH   512
#define HW   4096
#define NELT (512*256*256)

// scratch (static device allocs are allowed)
__device__ __align__(16) __nv_bfloat16 g_feats[CH * HW];   // 4 MB bf16 copy of feats
__device__ __align__(16) float         g_G[CH * CH];       // 1 MB gram (scaled)

// ---------------------------------------------------------------------------
// Kernel 1: fp32 -> bf16 convert, zero G, zero out
// ---------------------------------------------------------------------------
__global__ void __launch_bounds__(256) k_convert(const float* __restrict__ x,
                                                 float* __restrict__ out) {
    int gi = blockIdx.x * 256 + threadIdx.x;      // 524288 float4's
    float4 v = reinterpret_cast<const float4*>(x)[gi];
    __nv_bfloat162 p0, p1;
    p0.x = __float2bfloat16(v.x); p0.y = __float2bfloat16(v.y);
    p1.x = __float2bfloat16(v.z); p1.y = __float2bfloat16(v.w);
    reinterpret_cast<__nv_bfloat162*>(g_feats)[2 * gi + 0] = p0;
    reinterpret_cast<__nv_bfloat162*>(g_feats)[2 * gi + 1] = p1;
    if (gi < (CH * CH) / 4) {
        reinterpret_cast<float4*>(g_G)[gi] = make_float4(0.f, 0.f, 0.f, 0.f);
    }
    if (gi == 0) out[0] = 0.0f;
}

// ---------------------------------------------------------------------------
// Kernel 2: G = feats @ featsT / 2^20   (bf16 mma.sync, split-K=4)
// ---------------------------------------------------------------------------
__device__ __forceinline__ uint32_t smem_u32(const void* p) {
    return static_cast<uint32_t>(__cvta_generic_to_shared(p));
}
__device__ __forceinline__ void ldm_x4(uint32_t* d, uint32_t addr) {
    asm volatile("ldmatrix.sync.aligned.m8n8.x4.shared.b16 {%0,%1,%2,%3}, [%4];"
                 : "=r"(d[0]), "=r"(d[1]), "=r"(d[2]), "=r"(d[3]) : "r"(addr));
}
__device__ __forceinline__ void mma_bf16(float* c, const uint32_t* a, uint32_t b0, uint32_t b1) {
    asm volatile("mma.sync.aligned.m16n8k16.row.col.f32.bf16.bf16.f32 "
                 "{%0,%1,%2,%3},{%4,%5,%6,%7},{%8,%9},{%0,%1,%2,%3};"
                 : "+f"(c[0]), "+f"(c[1]), "+f"(c[2]), "+f"(c[3])
                 : "r"(a[0]), "r"(a[1]), "r"(a[2]), "r"(a[3]), "r"(b0), "r"(b1));
}

__global__ void __launch_bounds__(128) k_gemm() {
    const int m0 = blockIdx.y * 64;
    const int n0 = blockIdx.x * 64;
    const int kz = blockIdx.z * 1024;

    __shared__ __align__(16) __nv_bfloat16 As[64][72];
    __shared__ __align__(16) __nv_bfloat16 Bs[64][72];

    const int t = threadIdx.x;
    const int w = t >> 5, l = t & 31;
    const int wm = (w >> 1) * 32, wn = (w & 1) * 32;

    float acc[2][2][2][4];
    #pragma unroll
    for (int a = 0; a < 2; a++)
      #pragma unroll
      for (int b = 0; b < 2; b++)
        #pragma unroll
        for (int h = 0; h < 2; h++)
          #pragma unroll
          for (int q = 0; q < 4; q++) acc[a][b][h][q] = 0.f;

    const int lr = t >> 3;            // load row group 0..15
    const int lc = (t & 7) * 8;       // bf16 col (16B chunks)
    const int lrow = l & 15;          // ldmatrix row select
    const int lkh  = (l >> 4) * 8;    // ldmatrix k-half select

    for (int ks = 0; ks < 16; ks++) {
        const int kb = kz + ks * 64;
        #pragma unroll
        for (int p = 0; p < 4; p++) {
            *reinterpret_cast<uint4*>(&As[lr + p * 16][lc]) =
                *reinterpret_cast<const uint4*>(&g_feats[(m0 + lr + p * 16) * HW + kb + lc]);
            *reinterpret_cast<uint4*>(&Bs[lr + p * 16][lc]) =
                *reinterpret_cast<const uint4*>(&g_feats[(n0 + lr + p * 16) * HW + kb + lc]);
        }
        __syncthreads();

        #pragma unroll
        for (int k16 = 0; k16 < 4; k16++) {
            uint32_t afr[2][4], bfr[2][4];
            #pragma unroll
            for (int mt = 0; mt < 2; mt++)
                ldm_x4(afr[mt], smem_u32(&As[wm + mt * 16 + lrow][k16 * 16 + lkh]));
            #pragma unroll
            for (int nt = 0; nt < 2; nt++)
                ldm_x4(bfr[nt], smem_u32(&Bs[wn + nt * 16 + lrow][k16 * 16 + lkh]));
            #pragma unroll
            for (int mt = 0; mt < 2; mt++)
                #pragma unroll
                for (int nt = 0; nt < 2; nt++) {
                    mma_bf16(acc[mt][nt][0], afr[mt], bfr[nt][0], bfr[nt][2]);
                    mma_bf16(acc[mt][nt][1], afr[mt], bfr[nt][1], bfr[nt][3]);
                }
        }
        __syncthreads();
    }

    // epilogue: atomic accumulate (split-K), scaled by 1/2^20
    const float s = 1.0f / 1048576.0f;
    const int g = l >> 2, cc = (l & 3) * 2;
    #pragma unroll
    for (int mt = 0; mt < 2; mt++)
      #pragma unroll
      for (int nt = 0; nt < 2; nt++)
        #pragma unroll
        for (int h = 0; h < 2; h++) {
            const int row = m0 + wm + mt * 16 + g;
            const int col = n0 + wn + nt * 16 + h * 8 + cc;
            atomicAdd(&g_G[row * CH + col],           acc[mt][nt][h][0] * s);
            atomicAdd(&g_G[row * CH + col + 1],       acc[mt][nt][h][1] * s);
            atomicAdd(&g_G[(row + 8) * CH + col],     acc[mt][nt][h][2] * s);
            atomicAdd(&g_G[(row + 8) * CH + col + 1], acc[mt][nt][h][3] * s);
        }
}

// ---------------------------------------------------------------------------
// Kernel 3: loss = mean((G[(i+j)%512][(i+k)%512] - target[i,j,k])^2) * 1e6
// One CTA per (G-row r, half of j-range): G row cached in SMEM -> G costs 1MB
// of HBM total, target streams 134MB fully coalesced.
// ---------------------------------------------------------------------------
__global__ void __launch_bounds__(256) k_loss(const float* __restrict__ target,
                                              float* __restrict__ out) {
    __shared__ float sG[512];
    __shared__ float red[256];
    const int b  = blockIdx.x;       // 1024
    const int r  = b >> 1;
    const int j0 = (b & 1) * 128;
    const int t  = threadIdx.x;

    sG[t]       = g_G[r * CH + t];
    sG[t + 256] = g_G[r * CH + t + 256];
    __syncthreads();

    float accum = 0.f;
    #pragma unroll 4
    for (int j = j0; j < j0 + 128; j++) {
        const int i  = (r - j + 512) & 511;
        const float tv = target[i * 65536 + j * 256 + t];
        const float gv = sG[(i + t) & 511];
        const float d  = tv - gv;
        accum += d * d;
    }

    red[t] = accum;
    __syncthreads();
    #pragma unroll
    for (int s = 128; s > 0; s >>= 1) {
        if (t < s) red[t] += red[t + s];
        __syncthreads();
    }
    if (t == 0) atomicAdd(out, red[0] * (1.0e6f / 33554432.0f));
}

// ---------------------------------------------------------------------------
extern "C" void kernel_launch(void* const* d_in, const int* in_sizes, int n_in,
                              void* d_out, int out_size) {
    const float* x      = (const float*)d_in[0];   // (1,512,64,64) fp32
    const float* target = (const float*)d_in[1];   // (512,256,256) fp32
    float* out = (float*)d_out;

    k_convert<<<2048, 256>>>(x, out);
    dim3 gg(8, 8, 4);
    k_gemm<<<gg, 128>>>();
    k_loss<<<1024, 256>>>(target, out);
}

// round 2
// speedup vs baseline: 1.3007x; 1.3007x over previous
#include <cuda_runtime.h>
#include <cuda_bf16.h>
#include <cstdint>

#define CH   512
#define HW   4096

__device__ __align__(16) __nv_bfloat16 g_feats[CH * HW];   // 4 MB bf16 feats
__device__ __align__(16) float         g_G[CH * CH];       // 1 MB gram (scaled)

// ---------------------------------------------------------------------------
// Kernel 1: fp32 -> bf16 convert (vectorized), zero G, zero out
// ---------------------------------------------------------------------------
__global__ void __launch_bounds__(256) k_convert(const float* __restrict__ x,
                                                 float* __restrict__ out) {
    const int gi = blockIdx.x * 256 + threadIdx.x;   // 262144 threads
    const float4* xv = reinterpret_cast<const float4*>(x);
    uint2* fv = reinterpret_cast<uint2*>(g_feats);
    #pragma unroll
    for (int u = 0; u < 2; u++) {
        const int idx = gi + u * 262144;
        float4 v = xv[idx];
        __nv_bfloat162 p0, p1;
        p0.x = __float2bfloat16(v.x); p0.y = __float2bfloat16(v.y);
        p1.x = __float2bfloat16(v.z); p1.y = __float2bfloat16(v.w);
        uint2 pk;
        pk.x = *reinterpret_cast<uint32_t*>(&p0);
        pk.y = *reinterpret_cast<uint32_t*>(&p1);
        fv[idx] = pk;
    }
    if (gi < (CH * CH) / 4) {
        reinterpret_cast<float4*>(g_G)[gi] = make_float4(0.f, 0.f, 0.f, 0.f);
    }
    if (gi == 0) out[0] = 0.0f;
}

// ---------------------------------------------------------------------------
// Kernel 2: G = feats @ featsT / 2^20, symmetric tiles only + cp.async pipe
// ---------------------------------------------------------------------------
__device__ __forceinline__ uint32_t smem_u32(const void* p) {
    return static_cast<uint32_t>(__cvta_generic_to_shared(p));
}
__device__ __forceinline__ void cp_async16(uint32_t dst, const void* src) {
    asm volatile("cp.async.cg.shared.global [%0], [%1], 16;\n" :: "r"(dst), "l"(src));
}
__device__ __forceinline__ void ldm_x4(uint32_t* d, uint32_t addr) {
    asm volatile("ldmatrix.sync.aligned.m8n8.x4.shared.b16 {%0,%1,%2,%3}, [%4];"
                 : "=r"(d[0]), "=r"(d[1]), "=r"(d[2]), "=r"(d[3]) : "r"(addr));
}
__device__ __forceinline__ void mma_bf16(float* c, const uint32_t* a, uint32_t b0, uint32_t b1) {
    asm volatile("mma.sync.aligned.m16n8k16.row.col.f32.bf16.bf16.f32 "
                 "{%0,%1,%2,%3},{%4,%5,%6,%7},{%8,%9},{%0,%1,%2,%3};"
                 : "+f"(c[0]), "+f"(c[1]), "+f"(c[2]), "+f"(c[3])
                 : "r"(a[0]), "r"(a[1]), "r"(a[2]), "r"(a[3]), "r"(b0), "r"(b1));
}

__global__ void __launch_bounds__(128) k_gemm() {
    // map linear tile id -> upper-triangular (bi, bj), bi <= bj, 8x8 blocks
    int rem = blockIdx.x;           // 0..35
    int bi = 0;
    while (rem >= 8 - bi) { rem -= 8 - bi; bi++; }
    const int bj = bi + rem;
    const int m0 = bi * 64, n0 = bj * 64;
    const int kz = blockIdx.z * 1024;

    __shared__ __align__(16) __nv_bfloat16 As[2][64][72];
    __shared__ __align__(16) __nv_bfloat16 Bs[2][64][72];

    const int t = threadIdx.x;
    const int w = t >> 5, l = t & 31;
    const int wm = (w >> 1) * 32, wn = (w & 1) * 32;

    float acc[2][2][2][4];
    #pragma unroll
    for (int a = 0; a < 2; a++)
      #pragma unroll
      for (int b = 0; b < 2; b++)
        #pragma unroll
        for (int h = 0; h < 2; h++)
          #pragma unroll
          for (int q = 0; q < 4; q++) acc[a][b][h][q] = 0.f;

    const int lr = t >> 3;            // 0..15
    const int lc = (t & 7) * 8;       // bf16 col, 16B chunks
    const int lrow = l & 15;
    const int lkh  = (l >> 4) * 8;

    // stage loader
    auto load_stage = [&](int ks, int buf) {
        const int kb = kz + ks * 64;
        #pragma unroll
        for (int p = 0; p < 4; p++) {
            cp_async16(smem_u32(&As[buf][lr + p * 16][lc]),
                       &g_feats[(m0 + lr + p * 16) * HW + kb + lc]);
            cp_async16(smem_u32(&Bs[buf][lr + p * 16][lc]),
                       &g_feats[(n0 + lr + p * 16) * HW + kb + lc]);
        }
        asm volatile("cp.async.commit_group;\n" ::: "memory");
    };

    load_stage(0, 0);

    for (int ks = 0; ks < 16; ks++) {
        const int buf = ks & 1;
        if (ks < 15) {
            load_stage(ks + 1, buf ^ 1);
            asm volatile("cp.async.wait_group 1;\n" ::: "memory");
        } else {
            asm volatile("cp.async.wait_group 0;\n" ::: "memory");
        }
        __syncthreads();

        #pragma unroll
        for (int k16 = 0; k16 < 4; k16++) {
            uint32_t afr[2][4], bfr[2][4];
            #pragma unroll
            for (int mt = 0; mt < 2; mt++)
                ldm_x4(afr[mt], smem_u32(&As[buf][wm + mt * 16 + lrow][k16 * 16 + lkh]));
            #pragma unroll
            for (int nt = 0; nt < 2; nt++)
                ldm_x4(bfr[nt], smem_u32(&Bs[buf][wn + nt * 16 + lrow][k16 * 16 + lkh]));
            #pragma unroll
            for (int mt = 0; mt < 2; mt++)
                #pragma unroll
                for (int nt = 0; nt < 2; nt++) {
                    mma_bf16(acc[mt][nt][0], afr[mt], bfr[nt][0], bfr[nt][2]);
                    mma_bf16(acc[mt][nt][1], afr[mt], bfr[nt][1], bfr[nt][3]);
                }
        }
        __syncthreads();
    }

    // epilogue: split-K atomic accumulate, scaled; mirror for off-diag tiles
    const float s = 1.0f / 1048576.0f;
    const int g = l >> 2, cc = (l & 3) * 2;
    const bool mirror = (bi != bj);
    #pragma unroll
    for (int mt = 0; mt < 2; mt++)
      #pragma unroll
      for (int nt = 0; nt < 2; nt++)
        #pragma unroll
        for (int h = 0; h < 2; h++) {
            const int row = m0 + wm + mt * 16 + g;
            const int col = n0 + wn + nt * 16 + h * 8 + cc;
            const float v0 = acc[mt][nt][h][0] * s;
            const float v1 = acc[mt][nt][h][1] * s;
            const float v2 = acc[mt][nt][h][2] * s;
            const float v3 = acc[mt][nt][h][3] * s;
            atomicAdd(&g_G[row * CH + col],           v0);
            atomicAdd(&g_G[row * CH + col + 1],       v1);
            atomicAdd(&g_G[(row + 8) * CH + col],     v2);
            atomicAdd(&g_G[(row + 8) * CH + col + 1], v3);
            if (mirror) {
                atomicAdd(&g_G[col * CH + row],             v0);
                atomicAdd(&g_G[(col + 1) * CH + row],       v1);
                atomicAdd(&g_G[col * CH + row + 8],         v2);
                atomicAdd(&g_G[(col + 1) * CH + row + 8],   v3);
            }
        }
}

// ---------------------------------------------------------------------------
// Kernel 3: loss reduction. CTA per (G-row r, j half); 8-deep load batching.
// ---------------------------------------------------------------------------
__global__ void __launch_bounds__(256) k_loss(const float* __restrict__ target,
                                              float* __restrict__ out) {
    __shared__ float sG[512];
    __shared__ float red[256];
    const int b  = blockIdx.x;       // 1024
    const int r  = b >> 1;
    const int j0 = (b & 1) * 128;
    const int t  = threadIdx.x;

    sG[t]       = g_G[r * CH + t];
    sG[t + 256] = g_G[r * CH + t + 256];
    __syncthreads();

    float accum = 0.f;
    for (int jb = 0; jb < 128; jb += 8) {
        float tv[8];
        #pragma unroll
        for (int u = 0; u < 8; u++) {
            const int j = j0 + jb + u;
            const int i = (r - j + 512) & 511;
            tv[u] = target[i * 65536 + j * 256 + t];
        }
        #pragma unroll
        for (int u = 0; u < 8; u++) {
            const int j = j0 + jb + u;
            const int i = (r - j + 512) & 511;
            const float d = tv[u] - sG[(i + t) & 511];
            accum = fmaf(d, d, accum);
        }
    }

    red[t] = accum;
    __syncthreads();
    #pragma unroll
    for (int s = 128; s > 0; s >>= 1) {
        if (t < s) red[t] += red[t + s];
        __syncthreads();
    }
    if (t == 0) atomicAdd(out, red[0] * (1.0e6f / 33554432.0f));
}

// ---------------------------------------------------------------------------
extern "C" void kernel_launch(void* const* d_in, const int* in_sizes, int n_in,
                              void* d_out, int out_size) {
    const float* x      = (const float*)d_in[0];   // (1,512,64,64) fp32
    const float* target = (const float*)d_in[1];   // (512,256,256) fp32
    float* out = (float*)d_out;

    k_convert<<<1024, 256>>>(x, out);
    dim3 gg(36, 1, 4);
    k_gemm<<<gg, 128>>>();
    k_loss<<<1024, 256>>>(target, out);
}